// round 14
// baseline (speedup 1.0000x reference)
#include <cuda_runtime.h>
#include <cuda_fp16.h>
#include <cuda_bf16.h>
#include <math.h>
#include <stdint.h>

#define B_SZ   16384
#define IN_SZ  10
#define H_SZ   1024
#define R_COLS 6144
#define GD_ITERS_K 7
#define GD_LR_K 0.001f
#define GD_BLOCKS 512
#define ROWS_PER_BLOCK 32
#define RED_CH 32

// GEMM tiling (R10 config): CTA 256(M) x 128(N), BK=32 (fp16),
// 16 warps of 64x32, 3 stages, plain uint2 fragment loads.
#define BK 32
#define NITER (H_SZ / BK)
#define ROW_B 96                       /* 32 fp16 = 64B data + 32B pad */
#define A_TILE_B (256 * ROW_B)         /* 24576 */
#define B_TILE_B (128 * ROW_B)         /* 12288 */
#define STAGE_B (A_TILE_B + B_TILE_B)  /* 36864 */
#define NSTAGE 3
#define W_OFF_B   (NSTAGE * STAGE_B)             /* 110592 */
#define BIAS_OFF_B (W_OFF_B + 128 * IN_SZ * 4)   /* 115712 */
#define X_OFF_B   (BIAS_OFF_B + 128 * 4)         /* 116224 */
#define SMEM_TOTAL_B (X_OFF_B + 256 * IN_SZ * 4) /* 126464 */

// Scratch
__device__ float g_R[B_SZ * R_COLS];
__device__ __nv_bfloat16 g_Rh[B_SZ * R_COLS];      // bf16 shadow for GD
__device__ __half g_Ahh[B_SZ * H_SZ];              // fp16 hidden (row-major)
__device__ __half g_Uhh[4 * H_SZ * H_SZ];          // fp16 U (row-major)
__device__ float g_theta[R_COLS];
__device__ float g_part[GD_BLOCKS * R_COLS];
__device__ float g_part2[RED_CH * R_COLS];
__device__ int   g_argmax;

// ---------------------------------------------------------------------------
__device__ __forceinline__ uint32_t smem_u32(const void* p) {
    uint32_t a;
    asm("{ .reg .u64 t; cvta.to.shared.u64 t, %1; cvt.u32.u64 %0, t; }"
        : "=r"(a) : "l"(p));
    return a;
}
__device__ __forceinline__ uint32_t pack_f16x2(float lo, float hi) {
    uint32_t r;
    asm("cvt.rn.f16x2.f32 %0, %1, %2;" : "=r"(r) : "f"(hi), "f"(lo));
    return r;
}
__device__ __forceinline__ uint32_t pack_bf16x2(float lo, float hi) {
    uint32_t r;
    asm("cvt.rn.bf16x2.f32 %0, %1, %2;" : "=r"(r) : "f"(hi), "f"(lo));
    return r;
}
__device__ __forceinline__ void mma_f16_16x8x16(float* c, const uint32_t* a,
                                                const uint32_t* b) {
    asm volatile(
        "mma.sync.aligned.m16n8k16.row.col.f32.f16.f16.f32 "
        "{%0,%1,%2,%3}, {%4,%5,%6,%7}, {%8,%9}, {%0,%1,%2,%3};"
        : "+f"(c[0]), "+f"(c[1]), "+f"(c[2]), "+f"(c[3])
        : "r"(a[0]), "r"(a[1]), "r"(a[2]), "r"(a[3]), "r"(b[0]), "r"(b[1]));
}
#define CP_ASYNC16(dst, src) \
    asm volatile("cp.async.cg.shared.global [%0], [%1], 16;" :: "r"(dst), "l"(src) : "memory")
#define CP_COMMIT()  asm volatile("cp.async.commit_group;" ::: "memory")
#define CP_WAIT(n)   asm volatile("cp.async.wait_group %0;" :: "n"(n) : "memory")

// ---------------------------------------------------------------------------
// Prep: plain fp32 -> fp16 (16 elems/thread). Handles two arrays per launch.
// ---------------------------------------------------------------------------
__global__ void prep_f16_2(const float* __restrict__ srcA, __half* dstA, int n16A,
                           const float* __restrict__ srcB, __half* dstB, int n16B)
{
    int t = blockIdx.x * blockDim.x + threadIdx.x;
    const float* src; __half* dst;
    if (t < n16A) { src = srcA + (size_t)t * 16; dst = dstA + (size_t)t * 16; }
    else {
        t -= n16A;
        if (t >= n16B) return;
        src = srcB + (size_t)t * 16; dst = dstB + (size_t)t * 16;
    }
    float v[16];
    #pragma unroll
    for (int j = 0; j < 4; j++) {
        float4 f = ((const float4*)src)[j];
        v[4*j] = f.x; v[4*j+1] = f.y; v[4*j+2] = f.z; v[4*j+3] = f.w;
    }
    uint32_t w[8];
    #pragma unroll
    for (int j = 0; j < 8; j++) w[j] = pack_f16x2(v[2*j], v[2*j+1]);
    uint4* d4 = (uint4*)dst;
    d4[0] = make_uint4(w[0], w[1], w[2], w[3]);
    d4[1] = make_uint4(w[4], w[5], w[6], w[7]);
}

// ---------------------------------------------------------------------------
// Kernel 1: gate GEMM (R10 config). fp16 m16n8k16, 512 threads, 16 warps of
// 64x32, 3-stage cp.async pipeline, one barrier per k-iteration.
// ---------------------------------------------------------------------------
__device__ __forceinline__ void load_stage_(uint32_t smb, const __half* Abase,
                                            const __half* Bbase, int kit, int st,
                                            int tid)
{
    const int k0g = kit * BK;
    const uint32_t sb = smb + (uint32_t)st * STAGE_B;
    #pragma unroll
    for (int i = 0; i < 2; i++) {             // A: 1024 16B segs / 512 thr
        int idx = tid + i * 512;
        int row = idx >> 2, s4 = idx & 3;
        CP_ASYNC16(sb + (uint32_t)(row * ROW_B + s4 * 16),
                   Abase + (size_t)row * H_SZ + k0g + s4 * 8);
    }
    {                                          // B: 512 16B segs / 512 thr
        int row = tid >> 2, s4 = tid & 3;
        CP_ASYNC16(sb + (uint32_t)(A_TILE_B + row * ROW_B + s4 * 16),
                   Bbase + (size_t)row * H_SZ + k0g + s4 * 8);
    }
}

__global__ __launch_bounds__(512, 1)
void gate_gemm_mma(const float* __restrict__ x,
                   const float* __restrict__ W0, const float* __restrict__ W1,
                   const float* __restrict__ W2, const float* __restrict__ W3,
                   const float* __restrict__ b0, const float* __restrict__ b1,
                   const float* __restrict__ b2, const float* __restrict__ b3)
{
    extern __shared__ char sm[];
    const uint32_t smb = smem_u32(sm);

    const int tid  = threadIdx.x;
    const int lane = tid & 31, wid = tid >> 5;
    const int wm = (wid >> 2) * 64;            // 0,64,128,192
    const int wn = (wid & 3) * 32;             // 0,32,64,96
    const int g  = lane >> 2, tg = lane & 3;

    const int gate = blockIdx.x & 3;
    const int n0   = (blockIdx.x >> 2) * 128;
    const int m0   = blockIdx.y * 256;

    const float* W; const float* bias;
    switch (gate) {
        case 0:  W = W0; bias = b0; break;
        case 1:  W = W1; bias = b1; break;
        case 2:  W = W2; bias = b2; break;
        default: W = W3; bias = b3; break;
    }
    const __half* Abase = g_Ahh + (size_t)m0 * H_SZ;
    const __half* Bbase = g_Uhh + (size_t)gate * H_SZ * H_SZ + (size_t)n0 * H_SZ;

    // ---- prologue: stages 0 and 1 in flight ----
    load_stage_(smb, Abase, Bbase, 0, 0, tid); CP_COMMIT();
    load_stage_(smb, Abase, Bbase, 1, 1, tid); CP_COMMIT();

    // ---- stage x/W/bias for epilogue ----
    {
        float* smW = (float*)(sm + W_OFF_B);
        float* smB = (float*)(sm + BIAS_OFF_B);
        float* smX = (float*)(sm + X_OFF_B);
        for (int i = tid; i < 128 * IN_SZ; i += 512)
            smW[i] = __ldg(&W[(size_t)n0 * IN_SZ + i]);
        for (int i = tid; i < 256 * IN_SZ; i += 512)
            smX[i] = __ldg(&x[(size_t)m0 * IN_SZ + i]);
        if (tid < 128) smB[tid] = __ldg(&bias[n0 + tid]);
    }

    float acc[4][4][4];
    #pragma unroll
    for (int mi = 0; mi < 4; mi++)
        #pragma unroll
        for (int ni = 0; ni < 4; ni++)
            #pragma unroll
            for (int q = 0; q < 4; q++) acc[mi][ni][q] = 0.0f;

    int st = 0;
    for (int it = 0; it < NITER; it++) {
        if (it == NITER - 1) { CP_WAIT(0); } else { CP_WAIT(1); }
        __syncthreads();
        if (it + 2 < NITER) {
            int s2 = st + 2; if (s2 >= NSTAGE) s2 -= NSTAGE;
            load_stage_(smb, Abase, Bbase, it + 2, s2, tid);
            CP_COMMIT();
        }
        const char* As = sm + st * STAGE_B;
        const char* Bs = sm + st * STAGE_B + A_TILE_B;
        #pragma unroll
        for (int ks = 0; ks < 2; ks++) {
            const int koff = ks * 32 + tg * 8;
            uint32_t af[4][4], bf[4][2];
            #pragma unroll
            for (int mi = 0; mi < 4; mi++) {
                int r = wm + mi * 16 + g;
                uint2 alo = *(const uint2*)(As + r * ROW_B + koff);
                uint2 ahi = *(const uint2*)(As + (r + 8) * ROW_B + koff);
                af[mi][0] = alo.x; af[mi][1] = ahi.x;
                af[mi][2] = alo.y; af[mi][3] = ahi.y;
            }
            #pragma unroll
            for (int ni = 0; ni < 4; ni++) {
                int n = wn + ni * 8 + g;
                uint2 bv = *(const uint2*)(Bs + n * ROW_B + koff);
                bf[ni][0] = bv.x; bf[ni][1] = bv.y;
            }
            #pragma unroll
            for (int mi = 0; mi < 4; mi++)
                #pragma unroll
                for (int ni = 0; ni < 4; ni++)
                    mma_f16_16x8x16(acc[mi][ni], af[mi], bf[ni]);
        }
        if (++st == NSTAGE) st = 0;
    }

    // ---- epilogue: + bias + x@W^T (fp32), activation, store fp32 + bf16 ----
    const float* smW = (const float*)(sm + W_OFF_B);
    const float* smB = (const float*)(sm + BIAS_OFF_B);
    const float* smX = (const float*)(sm + X_OFF_B);
    #pragma unroll
    for (int mi = 0; mi < 4; mi++) {
        const int r0 = wm + mi * 16 + g;
        float xr0[IN_SZ], xr1[IN_SZ];
        #pragma unroll
        for (int t = 0; t < IN_SZ; t++) {
            xr0[t] = smX[r0 * IN_SZ + t];
            xr1[t] = smX[(r0 + 8) * IN_SZ + t];
        }
        #pragma unroll
        for (int ni = 0; ni < 4; ni++) {
            const int c0 = wn + ni * 8 + 2 * tg;
            float bv0 = smB[c0], bv1 = smB[c0 + 1];
            float v00 = acc[mi][ni][0] + bv0;
            float v01 = acc[mi][ni][1] + bv1;
            float v10 = acc[mi][ni][2] + bv0;
            float v11 = acc[mi][ni][3] + bv1;
            #pragma unroll
            for (int t = 0; t < IN_SZ; t++) {
                float w0 = smW[c0 * IN_SZ + t];
                float w1 = smW[(c0 + 1) * IN_SZ + t];
                v00 = fmaf(xr0[t], w0, v00); v01 = fmaf(xr0[t], w1, v01);
                v10 = fmaf(xr1[t], w0, v10); v11 = fmaf(xr1[t], w1, v11);
            }
            if (gate == 2) {
                v00 = tanhf(v00); v01 = tanhf(v01);
                v10 = tanhf(v10); v11 = tanhf(v11);
            } else {
                v00 = 1.0f / (1.0f + expf(-v00)); v01 = 1.0f / (1.0f + expf(-v01));
                v10 = 1.0f / (1.0f + expf(-v10)); v11 = 1.0f / (1.0f + expf(-v11));
            }
            size_t o0 = (size_t)(m0 + r0) * R_COLS + gate * H_SZ + n0 + c0;
            size_t o1 = (size_t)(m0 + r0 + 8) * R_COLS + gate * H_SZ + n0 + c0;
            *(float2*)&g_R[o0] = make_float2(v00, v01);
            *(float2*)&g_R[o1] = make_float2(v10, v11);
            *(uint32_t*)&g_Rh[o0] = pack_bf16x2(v00, v01);
            *(uint32_t*)&g_Rh[o1] = pack_bf16x2(v10, v11);
        }
    }
}

// ---------------------------------------------------------------------------
// Kernel 2: cellstate + fused GD iteration 0 (err0 = -mp).
// 2-row unroll with hoisted loads (doubles DRAM MLP).
// ---------------------------------------------------------------------------
__global__ __launch_bounds__(256) void cellstate_gd0(
    const float* __restrict__ c, const float* __restrict__ mp,
    float* __restrict__ out_c)
{
    const int tid = threadIdx.x;
    const int h = tid * 4;
    const int row0 = blockIdx.x * ROWS_PER_BLOCK;

    float gacc[6][4];
    #pragma unroll
    for (int q = 0; q < 6; q++)
        #pragma unroll
        for (int j = 0; j < 4; j++) gacc[q][j] = 0.0f;

    for (int r = 0; r < ROWS_PER_BLOCK; r += 2) {
        const int rowA = row0 + r, rowB = row0 + r + 1;
        const size_t baseA = (size_t)rowA * R_COLS + h;
        const size_t baseB = (size_t)rowB * R_COLS + h;
        // issue all 10 tile loads + 2 c loads up front (MLP ~ 12)
        float4 fA  = *(const float4*)&g_R[baseA + 0 * H_SZ];
        float4 iA  = *(const float4*)&g_R[baseA + 1 * H_SZ];
        float4 ctA = *(const float4*)&g_R[baseA + 2 * H_SZ];
        float4 oA  = *(const float4*)&g_R[baseA + 3 * H_SZ];
        float4 cA  = *(const float4*)&c[(size_t)rowA * H_SZ + h];
        float4 fB  = *(const float4*)&g_R[baseB + 0 * H_SZ];
        float4 iB  = *(const float4*)&g_R[baseB + 1 * H_SZ];
        float4 ctB = *(const float4*)&g_R[baseB + 2 * H_SZ];
        float4 oB  = *(const float4*)&g_R[baseB + 3 * H_SZ];
        float4 cB  = *(const float4*)&c[(size_t)rowB * H_SZ + h];
        const float eA = -__ldg(&mp[rowA]);
        const float eB = -__ldg(&mp[rowB]);

        float4 cnA, hsA, cnB, hsB;
        cnA.x = fA.x * cA.x + iA.x * ctA.x;  hsA.x = oA.x * tanhf(cnA.x);
        cnA.y = fA.y * cA.y + iA.y * ctA.y;  hsA.y = oA.y * tanhf(cnA.y);
        cnA.z = fA.z * cA.z + iA.z * ctA.z;  hsA.z = oA.z * tanhf(cnA.z);
        cnA.w = fA.w * cA.w + iA.w * ctA.w;  hsA.w = oA.w * tanhf(cnA.w);
        cnB.x = fB.x * cB.x + iB.x * ctB.x;  hsB.x = oB.x * tanhf(cnB.x);
        cnB.y = fB.y * cB.y + iB.y * ctB.y;  hsB.y = oB.y * tanhf(cnB.y);
        cnB.z = fB.z * cB.z + iB.z * ctB.z;  hsB.z = oB.z * tanhf(cnB.z);
        cnB.w = fB.w * cB.w + iB.w * ctB.w;  hsB.w = oB.w * tanhf(cnB.w);

        *(float4*)&g_R[baseA + 4 * H_SZ] = cnA;
        *(float4*)&g_R[baseA + 5 * H_SZ] = hsA;
        *(float4*)&g_R[baseB + 4 * H_SZ] = cnB;
        *(float4*)&g_R[baseB + 5 * H_SZ] = hsB;
        *(uint32_t*)&g_Rh[baseA + 4 * H_SZ]     = pack_bf16x2(cnA.x, cnA.y);
        *(uint32_t*)&g_Rh[baseA + 4 * H_SZ + 2] = pack_bf16x2(cnA.z, cnA.w);
        *(uint32_t*)&g_Rh[baseA + 5 * H_SZ]     = pack_bf16x2(hsA.x, hsA.y);
        *(uint32_t*)&g_Rh[baseA + 5 * H_SZ + 2] = pack_bf16x2(hsA.z, hsA.w);
        *(uint32_t*)&g_Rh[baseB + 4 * H_SZ]     = pack_bf16x2(cnB.x, cnB.y);
        *(uint32_t*)&g_Rh[baseB + 4 * H_SZ + 2] = pack_bf16x2(cnB.z, cnB.w);
        *(uint32_t*)&g_Rh[baseB + 5 * H_SZ]     = pack_bf16x2(hsB.x, hsB.y);
        *(uint32_t*)&g_Rh[baseB + 5 * H_SZ + 2] = pack_bf16x2(hsB.z, hsB.w);
        *(float4*)&out_c[(size_t)rowA * H_SZ + h] = cnA;
        *(float4*)&out_c[(size_t)rowB * H_SZ + h] = cnB;

        gacc[0][0] += eA * fA.x  + eB * fB.x;  gacc[0][1] += eA * fA.y  + eB * fB.y;
        gacc[0][2] += eA * fA.z  + eB * fB.z;  gacc[0][3] += eA * fA.w  + eB * fB.w;
        gacc[1][0] += eA * iA.x  + eB * iB.x;  gacc[1][1] += eA * iA.y  + eB * iB.y;
        gacc[1][2] += eA * iA.z  + eB * iB.z;  gacc[1][3] += eA * iA.w  + eB * iB.w;
        gacc[2][0] += eA * ctA.x + eB * ctB.x; gacc[2][1] += eA * ctA.y + eB * ctB.y;
        gacc[2][2] += eA * ctA.z + eB * ctB.z; gacc[2][3] += eA * ctA.w + eB * ctB.w;
        gacc[3][0] += eA * oA.x  + eB * oB.x;  gacc[3][1] += eA * oA.y  + eB * oB.y;
        gacc[3][2] += eA * oA.z  + eB * oB.z;  gacc[3][3] += eA * oA.w  + eB * oB.w;
        gacc[4][0] += eA * cnA.x + eB * cnB.x; gacc[4][1] += eA * cnA.y + eB * cnB.y;
        gacc[4][2] += eA * cnA.z + eB * cnB.z; gacc[4][3] += eA * cnA.w + eB * cnB.w;
        gacc[5][0] += eA * hsA.x + eB * hsB.x; gacc[5][1] += eA * hsA.y + eB * hsB.y;
        gacc[5][2] += eA * hsA.z + eB * hsB.z; gacc[5][3] += eA * hsA.w + eB * hsB.w;
    }
    float* P = &g_part[(size_t)blockIdx.x * R_COLS];
    #pragma unroll
    for (int q = 0; q < 6; q++)
        *(float4*)&P[q * H_SZ + h] = make_float4(gacc[q][0], gacc[q][1], gacc[q][2], gacc[q][3]);
}

// ---------------------------------------------------------------------------
// Kernel 3: fused GD pass, double-buffered 4-row batches.
// ---------------------------------------------------------------------------
__global__ __launch_bounds__(256) void gd_pass(const float* __restrict__ mp)
{
    __shared__ float red_s[4][8];
    __shared__ float err_s[4];
    const int tid = threadIdx.x;
    const int lane = tid & 31, wrp = tid >> 5;
    const int cbase = tid * 24;

    float th[24], gacc[24];
    #pragma unroll
    for (int j = 0; j < 24; j++) { th[j] = g_theta[cbase + j]; gacc[j] = 0.0f; }

    const int row0 = blockIdx.x * ROWS_PER_BLOCK;
    uint4 u[2][4][3];
    #pragma unroll
    for (int rr = 0; rr < 4; rr++) {
        const uint4* R4 = (const uint4*)&g_Rh[(size_t)(row0 + rr) * R_COLS];
        #pragma unroll
        for (int j = 0; j < 3; j++) u[0][rr][j] = R4[tid * 3 + j];
    }

    #pragma unroll
    for (int batch = 0; batch < ROWS_PER_BLOCK / 4; batch++) {
        const int p = batch & 1;
        if (batch + 1 < ROWS_PER_BLOCK / 4) {
            const int rn = row0 + (batch + 1) * 4;
            #pragma unroll
            for (int rr = 0; rr < 4; rr++) {
                const uint4* R4 = (const uint4*)&g_Rh[(size_t)(rn + rr) * R_COLS];
                #pragma unroll
                for (int j = 0; j < 3; j++) u[p ^ 1][rr][j] = R4[tid * 3 + j];
            }
        }
        const int rb = row0 + batch * 4;
        float dots[4];
        #pragma unroll
        for (int rr = 0; rr < 4; rr++) {
            float dot = 0.0f;
            #pragma unroll
            for (int j = 0; j < 3; j++) {
                const uint32_t* w = (const uint32_t*)&u[p][rr][j];
                #pragma unroll
                for (int q = 0; q < 4; q++) {
                    dot = fmaf(__uint_as_float(w[q] << 16),         th[j*8 + q*2],     dot);
                    dot = fmaf(__uint_as_float(w[q] & 0xFFFF0000u), th[j*8 + q*2 + 1], dot);
                }
            }
            dots[rr] = dot;
        }
        #pragma unroll
        for (int off = 16; off; off >>= 1) {
            #pragma unroll
            for (int rr = 0; rr < 4; rr++)
                dots[rr] += __shfl_xor_sync(0xffffffffu, dots[rr], off);
        }
        if (lane == 0) {
            #pragma unroll
            for (int rr = 0; rr < 4; rr++) red_s[rr][wrp] = dots[rr];
        }
        __syncthreads();
        if (tid < 4) {
            float s = 0.0f;
            #pragma unroll
            for (int w = 0; w < 8; w++) s += red_s[tid][w];
            err_s[tid] = s - __ldg(&mp[rb + tid]);
        }
        __syncthreads();
        #pragma unroll
        for (int rr = 0; rr < 4; rr++) {
            const float err = err_s[rr];
            #pragma unroll
            for (int j = 0; j < 3; j++) {
                const uint32_t* w = (const uint32_t*)&u[p][rr][j];
                #pragma unroll
                for (int q = 0; q < 4; q++) {
                    gacc[j*8 + q*2]     = fmaf(err, __uint_as_float(w[q] << 16),         gacc[j*8 + q*2]);
                    gacc[j*8 + q*2 + 1] = fmaf(err, __uint_as_float(w[q] & 0xFFFF0000u), gacc[j*8 + q*2 + 1]);
                }
            }
        }
    }
    float* P = &g_part[(size_t)blockIdx.x * R_COLS + cbase];
    #pragma unroll
    for (int j = 0; j < 24; j++) P[j] = gacc[j];
}

// ---------------------------------------------------------------------------
// Two-stage deterministic reduce: 512 -> 32 -> theta
// ---------------------------------------------------------------------------
__global__ void gd_reduce1()
{
    int j = blockIdx.x * blockDim.x + threadIdx.x;
    int chunk = blockIdx.y;
    int b0 = chunk * (GD_BLOCKS / RED_CH);
    float s0 = 0.f, s1 = 0.f;
    #pragma unroll
    for (int b = 0; b < GD_BLOCKS / RED_CH; b += 2) {
        s0 += g_part[(size_t)(b0 + b) * R_COLS + j];
        s1 += g_part[(size_t)(b0 + b + 1) * R_COLS + j];
    }
    g_part2[(size_t)chunk * R_COLS + j] = s0 + s1;
}

__global__ void gd_reduce2_first(float scale)
{
    int j = blockIdx.x * blockDim.x + threadIdx.x;
    float s0 = 0.f, s1 = 0.f, s2 = 0.f, s3 = 0.f;
    #pragma unroll
    for (int b = 0; b < RED_CH; b += 4) {
        s0 += g_part2[(size_t)(b + 0) * R_COLS + j];
        s1 += g_part2[(size_t)(b + 1) * R_COLS + j];
        s2 += g_part2[(size_t)(b + 2) * R_COLS + j];
        s3 += g_part2[(size_t)(b + 3) * R_COLS + j];
    }
    g_theta[j] = -scale * ((s0 + s1) + (s2 + s3));
}

__global__ void gd_reduce2(float scale)
{
    int j = blockIdx.x * blockDim.x + threadIdx.x;
    float s0 = 0.f, s1 = 0.f, s2 = 0.f, s3 = 0.f;
    #pragma unroll
    for (int b = 0; b < RED_CH; b += 4) {
        s0 += g_part2[(size_t)(b + 0) * R_COLS + j];
        s1 += g_part2[(size_t)(b + 1) * R_COLS + j];
        s2 += g_part2[(size_t)(b + 2) * R_COLS + j];
        s3 += g_part2[(size_t)(b + 3) * R_COLS + j];
    }
    g_theta[j] -= scale * ((s0 + s1) + (s2 + s3));
}

__global__ void argmax_kernel()
{
    __shared__ float sums[6];
    int w = threadIdx.x >> 5, lane = threadIdx.x & 31;
    if (threadIdx.x < 192) {
        float s = 0.0f;
        for (int i = lane; i < H_SZ; i += 32) s += fabsf(g_theta[w * H_SZ + i]);
        #pragma unroll
        for (int off = 16; off; off >>= 1)
            s += __shfl_xor_sync(0xffffffffu, s, off);
        if (lane == 0) sums[w] = s;
    }
    __syncthreads();
    if (threadIdx.x == 0) {
        int best = 0; float bv = sums[0];
        #pragma unroll
        for (int g = 1; g < 6; g++)
            if (sums[g] > bv) { bv = sums[g]; best = g; }
        g_argmax = best;
    }
}

// 16 floats per thread (4 independent float4 loads -> MLP=4)
__global__ void gather_kernel(float* __restrict__ out_h)
{
    int t = blockIdx.x * blockDim.x + threadIdx.x;
    int e = t * 16;
    int b = e >> 10;
    int h = e & 1023;
    const int idx = g_argmax;
    const float4* src = (const float4*)&g_R[(size_t)b * R_COLS + idx * H_SZ + h];
    float4 v0 = src[0], v1 = src[1], v2 = src[2], v3 = src[3];
    float4* dst = (float4*)&out_h[e];
    dst[0] = v0; dst[1] = v1; dst[2] = v2; dst[3] = v3;
}

// ---------------------------------------------------------------------------
extern "C" void kernel_launch(void* const* d_in, const int* in_sizes, int n_in,
                              void* d_out, int out_size)
{
    const float* x      = (const float*)d_in[0];
    const float* hidden = (const float*)d_in[1];
    const float* c      = (const float*)d_in[2];
    const float* mp     = (const float*)d_in[3];
    const float* Wf_w = (const float*)d_in[4];
    const float* Wf_b = (const float*)d_in[5];
    const float* Uf_w = (const float*)d_in[6];
    const float* Wi_w = (const float*)d_in[7];
    const float* Wi_b = (const float*)d_in[8];
    const float* Ui_w = (const float*)d_in[9];
    const float* Wc_w = (const float*)d_in[10];
    const float* Wc_b = (const float*)d_in[11];
    const float* Uc_w = (const float*)d_in[12];
    const float* Wo_w = (const float*)d_in[13];
    const float* Wo_b = (const float*)d_in[14];
    const float* Uo_w = (const float*)d_in[15];

    float* out_h = (float*)d_out;
    float* out_c = out_h + (size_t)B_SZ * H_SZ;

    cudaFuncSetAttribute(gate_gemm_mma,
                         cudaFuncAttributeMaxDynamicSharedMemorySize, SMEM_TOTAL_B);

    __half* Ahh; cudaGetSymbolAddress((void**)&Ahh, g_Ahh);
    __half* Uhh; cudaGetSymbolAddress((void**)&Uhh, g_Uhh);

    const int nH16 = B_SZ * H_SZ / 16;          // 1048576
    const int nU16 = H_SZ * H_SZ / 16;          // 65536

    // GEMM is the 4th launch (the slot ncu captures)
    prep_f16_2<<<(nH16 + nU16 + 255) / 256, 256>>>(
        hidden, Ahh, nH16, Uf_w, Uhh + 0 * (size_t)H_SZ * H_SZ, nU16);
    prep_f16_2<<<(2 * nU16 + 255) / 256, 256>>>(
        Ui_w, Uhh + 1 * (size_t)H_SZ * H_SZ, nU16,
        Uc_w, Uhh + 2 * (size_t)H_SZ * H_SZ, nU16);
    prep_f16_2<<<(nU16 + 255) / 256, 256>>>(
        Uo_w, Uhh + 3 * (size_t)H_SZ * H_SZ, nU16,
        Uo_w, Uhh + 3 * (size_t)H_SZ * H_SZ, 0);

    dim3 ggrid(32, 64);
    gate_gemm_mma<<<ggrid, 512, SMEM_TOTAL_B>>>(x,
                                                Wf_w, Wi_w, Wc_w, Wo_w,
                                                Wf_b, Wi_b, Wc_b, Wo_b);

    const float scale = 2.0f * GD_LR_K / (float)B_SZ;
    dim3 r1grid(R_COLS / 256, RED_CH);

    cellstate_gd0<<<GD_BLOCKS, 256>>>(c, mp, out_c);
    gd_reduce1<<<r1grid, 256>>>();
    gd_reduce2_first<<<R_COLS / 256, 256>>>(scale);

    for (int it = 1; it < GD_ITERS_K; it++) {
        gd_pass<<<GD_BLOCKS, 256>>>(mp);
        gd_reduce1<<<r1grid, 256>>>();
        gd_reduce2<<<R_COLS / 256, 256>>>(scale);
    }

    argmax_kernel<<<1, 192>>>();
    gather_kernel<<<(B_SZ * H_SZ / 16) / 256, 256>>>(out_h);
}

// round 17
// speedup vs baseline: 1.4442x; 1.4442x over previous
#include <cuda_runtime.h>
#include <cuda_fp16.h>
#include <cuda_bf16.h>
#include <math.h>
#include <stdint.h>

#define B_SZ   16384
#define IN_SZ  10
#define H_SZ   1024
#define R_COLS 6144
#define GD_ITERS_K 7
#define GD_LR_K 0.001f
#define GD_BLOCKS 512
#define ROWS_PER_BLOCK 32
#define RED_CH 32

// GEMM tiling (R10 config): CTA 256(M) x 128(N), BK=32 (fp16),
// 16 warps of 64x32, 3 stages, plain uint2 fragment loads.
#define BK 32
#define NITER (H_SZ / BK)
#define ROW_B 96                       /* 32 fp16 = 64B data + 32B pad */
#define A_TILE_B (256 * ROW_B)         /* 24576 */
#define B_TILE_B (128 * ROW_B)         /* 12288 */
#define STAGE_B (A_TILE_B + B_TILE_B)  /* 36864 */
#define NSTAGE 3
#define W_OFF_B   (NSTAGE * STAGE_B)             /* 110592 */
#define BIAS_OFF_B (W_OFF_B + 128 * IN_SZ * 4)   /* 115712 */
#define X_OFF_B   (BIAS_OFF_B + 128 * 4)         /* 116224 */
#define SMEM_TOTAL_B (X_OFF_B + 256 * IN_SZ * 4) /* 126464 */

// Scratch
__device__ float g_R[B_SZ * R_COLS];
__device__ __nv_bfloat16 g_Rh[B_SZ * R_COLS];      // bf16 shadow for GD
__device__ __half g_Ahh[B_SZ * H_SZ];              // fp16 hidden (row-major)
__device__ __half g_Uhh[4 * H_SZ * H_SZ];          // fp16 U (row-major)
__device__ float g_theta[R_COLS];
__device__ float g_part[GD_BLOCKS * R_COLS];
__device__ float g_part2[RED_CH * R_COLS];
__device__ int   g_argmax;

// ---------------------------------------------------------------------------
__device__ __forceinline__ uint32_t smem_u32(const void* p) {
    uint32_t a;
    asm("{ .reg .u64 t; cvta.to.shared.u64 t, %1; cvt.u32.u64 %0, t; }"
        : "=r"(a) : "l"(p));
    return a;
}
__device__ __forceinline__ uint32_t pack_f16x2(float lo, float hi) {
    uint32_t r;
    asm("cvt.rn.f16x2.f32 %0, %1, %2;" : "=r"(r) : "f"(hi), "f"(lo));
    return r;
}
__device__ __forceinline__ uint32_t pack_bf16x2(float lo, float hi) {
    uint32_t r;
    asm("cvt.rn.bf16x2.f32 %0, %1, %2;" : "=r"(r) : "f"(hi), "f"(lo));
    return r;
}
__device__ __forceinline__ void mma_f16_16x8x16(float* c, const uint32_t* a,
                                                const uint32_t* b) {
    asm volatile(
        "mma.sync.aligned.m16n8k16.row.col.f32.f16.f16.f32 "
        "{%0,%1,%2,%3}, {%4,%5,%6,%7}, {%8,%9}, {%0,%1,%2,%3};"
        : "+f"(c[0]), "+f"(c[1]), "+f"(c[2]), "+f"(c[3])
        : "r"(a[0]), "r"(a[1]), "r"(a[2]), "r"(a[3]), "r"(b[0]), "r"(b[1]));
}
#define CP_ASYNC16(dst, src) \
    asm volatile("cp.async.cg.shared.global [%0], [%1], 16;" :: "r"(dst), "l"(src) : "memory")
#define CP_COMMIT()  asm volatile("cp.async.commit_group;" ::: "memory")
#define CP_WAIT(n)   asm volatile("cp.async.wait_group %0;" :: "n"(n) : "memory")

// ---------------------------------------------------------------------------
// Prep: plain fp32 -> fp16 (16 elems/thread). Handles two arrays per launch.
// ---------------------------------------------------------------------------
__global__ void prep_f16_2(const float* __restrict__ srcA, __half* dstA, int n16A,
                           const float* __restrict__ srcB, __half* dstB, int n16B)
{
    int t = blockIdx.x * blockDim.x + threadIdx.x;
    const float* src; __half* dst;
    if (t < n16A) { src = srcA + (size_t)t * 16; dst = dstA + (size_t)t * 16; }
    else {
        t -= n16A;
        if (t >= n16B) return;
        src = srcB + (size_t)t * 16; dst = dstB + (size_t)t * 16;
    }
    float v[16];
    #pragma unroll
    for (int j = 0; j < 4; j++) {
        float4 f = ((const float4*)src)[j];
        v[4*j] = f.x; v[4*j+1] = f.y; v[4*j+2] = f.z; v[4*j+3] = f.w;
    }
    uint32_t w[8];
    #pragma unroll
    for (int j = 0; j < 8; j++) w[j] = pack_f16x2(v[2*j], v[2*j+1]);
    uint4* d4 = (uint4*)dst;
    d4[0] = make_uint4(w[0], w[1], w[2], w[3]);
    d4[1] = make_uint4(w[4], w[5], w[6], w[7]);
}

// ---------------------------------------------------------------------------
// Kernel 1: gate GEMM (R10 config). fp16 m16n8k16, 512 threads, 16 warps of
// 64x32, 3-stage cp.async pipeline, one barrier per k-iteration.
// ---------------------------------------------------------------------------
__device__ __forceinline__ void load_stage_(uint32_t smb, const __half* Abase,
                                            const __half* Bbase, int kit, int st,
                                            int tid)
{
    const int k0g = kit * BK;
    const uint32_t sb = smb + (uint32_t)st * STAGE_B;
    #pragma unroll
    for (int i = 0; i < 2; i++) {             // A: 1024 16B segs / 512 thr
        int idx = tid + i * 512;
        int row = idx >> 2, s4 = idx & 3;
        CP_ASYNC16(sb + (uint32_t)(row * ROW_B + s4 * 16),
                   Abase + (size_t)row * H_SZ + k0g + s4 * 8);
    }
    {                                          // B: 512 16B segs / 512 thr
        int row = tid >> 2, s4 = tid & 3;
        CP_ASYNC16(sb + (uint32_t)(A_TILE_B + row * ROW_B + s4 * 16),
                   Bbase + (size_t)row * H_SZ + k0g + s4 * 8);
    }
}

__global__ __launch_bounds__(512, 1)
void gate_gemm_mma(const float* __restrict__ x,
                   const float* __restrict__ W0, const float* __restrict__ W1,
                   const float* __restrict__ W2, const float* __restrict__ W3,
                   const float* __restrict__ b0, const float* __restrict__ b1,
                   const float* __restrict__ b2, const float* __restrict__ b3)
{
    extern __shared__ char sm[];
    const uint32_t smb = smem_u32(sm);

    const int tid  = threadIdx.x;
    const int lane = tid & 31, wid = tid >> 5;
    const int wm = (wid >> 2) * 64;            // 0,64,128,192
    const int wn = (wid & 3) * 32;             // 0,32,64,96
    const int g  = lane >> 2, tg = lane & 3;

    const int gate = blockIdx.x & 3;
    const int n0   = (blockIdx.x >> 2) * 128;
    const int m0   = blockIdx.y * 256;

    const float* W; const float* bias;
    switch (gate) {
        case 0:  W = W0; bias = b0; break;
        case 1:  W = W1; bias = b1; break;
        case 2:  W = W2; bias = b2; break;
        default: W = W3; bias = b3; break;
    }
    const __half* Abase = g_Ahh + (size_t)m0 * H_SZ;
    const __half* Bbase = g_Uhh + (size_t)gate * H_SZ * H_SZ + (size_t)n0 * H_SZ;

    // ---- prologue: stages 0 and 1 in flight ----
    load_stage_(smb, Abase, Bbase, 0, 0, tid); CP_COMMIT();
    load_stage_(smb, Abase, Bbase, 1, 1, tid); CP_COMMIT();

    // ---- stage x/W/bias for epilogue ----
    {
        float* smW = (float*)(sm + W_OFF_B);
        float* smB = (float*)(sm + BIAS_OFF_B);
        float* smX = (float*)(sm + X_OFF_B);
        for (int i = tid; i < 128 * IN_SZ; i += 512)
            smW[i] = __ldg(&W[(size_t)n0 * IN_SZ + i]);
        for (int i = tid; i < 256 * IN_SZ; i += 512)
            smX[i] = __ldg(&x[(size_t)m0 * IN_SZ + i]);
        if (tid < 128) smB[tid] = __ldg(&bias[n0 + tid]);
    }

    float acc[4][4][4];
    #pragma unroll
    for (int mi = 0; mi < 4; mi++)
        #pragma unroll
        for (int ni = 0; ni < 4; ni++)
            #pragma unroll
            for (int q = 0; q < 4; q++) acc[mi][ni][q] = 0.0f;

    int st = 0;
    for (int it = 0; it < NITER; it++) {
        if (it == NITER - 1) { CP_WAIT(0); } else { CP_WAIT(1); }
        __syncthreads();
        if (it + 2 < NITER) {
            int s2 = st + 2; if (s2 >= NSTAGE) s2 -= NSTAGE;
            load_stage_(smb, Abase, Bbase, it + 2, s2, tid);
            CP_COMMIT();
        }
        const char* As = sm + st * STAGE_B;
        const char* Bs = sm + st * STAGE_B + A_TILE_B;
        #pragma unroll
        for (int ks = 0; ks < 2; ks++) {
            const int koff = ks * 32 + tg * 8;
            uint32_t af[4][4], bf[4][2];
            #pragma unroll
            for (int mi = 0; mi < 4; mi++) {
                int r = wm + mi * 16 + g;
                uint2 alo = *(const uint2*)(As + r * ROW_B + koff);
                uint2 ahi = *(const uint2*)(As + (r + 8) * ROW_B + koff);
                af[mi][0] = alo.x; af[mi][1] = ahi.x;
                af[mi][2] = alo.y; af[mi][3] = ahi.y;
            }
            #pragma unroll
            for (int ni = 0; ni < 4; ni++) {
                int n = wn + ni * 8 + g;
                uint2 bv = *(const uint2*)(Bs + n * ROW_B + koff);
                bf[ni][0] = bv.x; bf[ni][1] = bv.y;
            }
            #pragma unroll
            for (int mi = 0; mi < 4; mi++)
                #pragma unroll
                for (int ni = 0; ni < 4; ni++)
                    mma_f16_16x8x16(acc[mi][ni], af[mi], bf[ni]);
        }
        if (++st == NSTAGE) st = 0;
    }

    // ---- epilogue: + bias + x@W^T (fp32), activation, store fp32 + bf16 ----
    const float* smW = (const float*)(sm + W_OFF_B);
    const float* smB = (const float*)(sm + BIAS_OFF_B);
    const float* smX = (const float*)(sm + X_OFF_B);
    #pragma unroll
    for (int mi = 0; mi < 4; mi++) {
        const int r0 = wm + mi * 16 + g;
        float xr0[IN_SZ], xr1[IN_SZ];
        #pragma unroll
        for (int t = 0; t < IN_SZ; t++) {
            xr0[t] = smX[r0 * IN_SZ + t];
            xr1[t] = smX[(r0 + 8) * IN_SZ + t];
        }
        #pragma unroll
        for (int ni = 0; ni < 4; ni++) {
            const int c0 = wn + ni * 8 + 2 * tg;
            float bv0 = smB[c0], bv1 = smB[c0 + 1];
            float v00 = acc[mi][ni][0] + bv0;
            float v01 = acc[mi][ni][1] + bv1;
            float v10 = acc[mi][ni][2] + bv0;
            float v11 = acc[mi][ni][3] + bv1;
            #pragma unroll
            for (int t = 0; t < IN_SZ; t++) {
                float w0 = smW[c0 * IN_SZ + t];
                float w1 = smW[(c0 + 1) * IN_SZ + t];
                v00 = fmaf(xr0[t], w0, v00); v01 = fmaf(xr0[t], w1, v01);
                v10 = fmaf(xr1[t], w0, v10); v11 = fmaf(xr1[t], w1, v11);
            }
            if (gate == 2) {
                v00 = tanhf(v00); v01 = tanhf(v01);
                v10 = tanhf(v10); v11 = tanhf(v11);
            } else {
                v00 = 1.0f / (1.0f + expf(-v00)); v01 = 1.0f / (1.0f + expf(-v01));
                v10 = 1.0f / (1.0f + expf(-v10)); v11 = 1.0f / (1.0f + expf(-v11));
            }
            size_t o0 = (size_t)(m0 + r0) * R_COLS + gate * H_SZ + n0 + c0;
            size_t o1 = (size_t)(m0 + r0 + 8) * R_COLS + gate * H_SZ + n0 + c0;
            *(float2*)&g_R[o0] = make_float2(v00, v01);
            *(float2*)&g_R[o1] = make_float2(v10, v11);
            *(uint32_t*)&g_Rh[o0] = pack_bf16x2(v00, v01);
            *(uint32_t*)&g_Rh[o1] = pack_bf16x2(v10, v11);
        }
    }
}

// ---------------------------------------------------------------------------
// Kernel 2: cellstate + fused GD iteration 0 (err0 = -mp). (R10 version)
// ---------------------------------------------------------------------------
__global__ __launch_bounds__(256) void cellstate_gd0(
    const float* __restrict__ c, const float* __restrict__ mp,
    float* __restrict__ out_c)
{
    const int tid = threadIdx.x;
    const int h = tid * 4;
    const int row0 = blockIdx.x * ROWS_PER_BLOCK;

    float gacc[6][4];
    #pragma unroll
    for (int q = 0; q < 6; q++)
        #pragma unroll
        for (int j = 0; j < 4; j++) gacc[q][j] = 0.0f;

    for (int r = 0; r < ROWS_PER_BLOCK; r++) {
        const int row = row0 + r;
        const size_t base = (size_t)row * R_COLS + h;
        float4 f  = *(const float4*)&g_R[base + 0 * H_SZ];
        float4 ii = *(const float4*)&g_R[base + 1 * H_SZ];
        float4 ct = *(const float4*)&g_R[base + 2 * H_SZ];
        float4 o  = *(const float4*)&g_R[base + 3 * H_SZ];
        float4 co = *(const float4*)&c[(size_t)row * H_SZ + h];
        float4 cn, hs;
        cn.x = f.x * co.x + ii.x * ct.x;  hs.x = o.x * tanhf(cn.x);
        cn.y = f.y * co.y + ii.y * ct.y;  hs.y = o.y * tanhf(cn.y);
        cn.z = f.z * co.z + ii.z * ct.z;  hs.z = o.z * tanhf(cn.z);
        cn.w = f.w * co.w + ii.w * ct.w;  hs.w = o.w * tanhf(cn.w);
        *(float4*)&g_R[base + 4 * H_SZ] = cn;
        *(float4*)&g_R[base + 5 * H_SZ] = hs;
        *(uint32_t*)&g_Rh[base + 4 * H_SZ]     = pack_bf16x2(cn.x, cn.y);
        *(uint32_t*)&g_Rh[base + 4 * H_SZ + 2] = pack_bf16x2(cn.z, cn.w);
        *(uint32_t*)&g_Rh[base + 5 * H_SZ]     = pack_bf16x2(hs.x, hs.y);
        *(uint32_t*)&g_Rh[base + 5 * H_SZ + 2] = pack_bf16x2(hs.z, hs.w);
        *(float4*)&out_c[(size_t)row * H_SZ + h] = cn;

        const float e = -__ldg(&mp[row]);
        gacc[0][0] = fmaf(e, f.x,  gacc[0][0]); gacc[0][1] = fmaf(e, f.y,  gacc[0][1]);
        gacc[0][2] = fmaf(e, f.z,  gacc[0][2]); gacc[0][3] = fmaf(e, f.w,  gacc[0][3]);
        gacc[1][0] = fmaf(e, ii.x, gacc[1][0]); gacc[1][1] = fmaf(e, ii.y, gacc[1][1]);
        gacc[1][2] = fmaf(e, ii.z, gacc[1][2]); gacc[1][3] = fmaf(e, ii.w, gacc[1][3]);
        gacc[2][0] = fmaf(e, ct.x, gacc[2][0]); gacc[2][1] = fmaf(e, ct.y, gacc[2][1]);
        gacc[2][2] = fmaf(e, ct.z, gacc[2][2]); gacc[2][3] = fmaf(e, ct.w, gacc[2][3]);
        gacc[3][0] = fmaf(e, o.x,  gacc[3][0]); gacc[3][1] = fmaf(e, o.y,  gacc[3][1]);
        gacc[3][2] = fmaf(e, o.z,  gacc[3][2]); gacc[3][3] = fmaf(e, o.w,  gacc[3][3]);
        gacc[4][0] = fmaf(e, cn.x, gacc[4][0]); gacc[4][1] = fmaf(e, cn.y, gacc[4][1]);
        gacc[4][2] = fmaf(e, cn.z, gacc[4][2]); gacc[4][3] = fmaf(e, cn.w, gacc[4][3]);
        gacc[5][0] = fmaf(e, hs.x, gacc[5][0]); gacc[5][1] = fmaf(e, hs.y, gacc[5][1]);
        gacc[5][2] = fmaf(e, hs.z, gacc[5][2]); gacc[5][3] = fmaf(e, hs.w, gacc[5][3]);
    }
    float* P = &g_part[(size_t)blockIdx.x * R_COLS];
    #pragma unroll
    for (int q = 0; q < 6; q++)
        *(float4*)&P[q * H_SZ + h] = make_float4(gacc[q][0], gacc[q][1], gacc[q][2], gacc[q][3]);
}

// ---------------------------------------------------------------------------
// Kernel 3: fused GD pass, double-buffered 4-row batches.
// ---------------------------------------------------------------------------
__global__ __launch_bounds__(256) void gd_pass(const float* __restrict__ mp)
{
    __shared__ float red_s[4][8];
    __shared__ float err_s[4];
    const int tid = threadIdx.x;
    const int lane = tid & 31, wrp = tid >> 5;
    const int cbase = tid * 24;

    float th[24], gacc[24];
    #pragma unroll
    for (int j = 0; j < 24; j++) { th[j] = g_theta[cbase + j]; gacc[j] = 0.0f; }

    const int row0 = blockIdx.x * ROWS_PER_BLOCK;
    uint4 u[2][4][3];
    #pragma unroll
    for (int rr = 0; rr < 4; rr++) {
        const uint4* R4 = (const uint4*)&g_Rh[(size_t)(row0 + rr) * R_COLS];
        #pragma unroll
        for (int j = 0; j < 3; j++) u[0][rr][j] = R4[tid * 3 + j];
    }

    #pragma unroll
    for (int batch = 0; batch < ROWS_PER_BLOCK / 4; batch++) {
        const int p = batch & 1;
        if (batch + 1 < ROWS_PER_BLOCK / 4) {
            const int rn = row0 + (batch + 1) * 4;
            #pragma unroll
            for (int rr = 0; rr < 4; rr++) {
                const uint4* R4 = (const uint4*)&g_Rh[(size_t)(rn + rr) * R_COLS];
                #pragma unroll
                for (int j = 0; j < 3; j++) u[p ^ 1][rr][j] = R4[tid * 3 + j];
            }
        }
        const int rb = row0 + batch * 4;
        float dots[4];
        #pragma unroll
        for (int rr = 0; rr < 4; rr++) {
            float dot = 0.0f;
            #pragma unroll
            for (int j = 0; j < 3; j++) {
                const uint32_t* w = (const uint32_t*)&u[p][rr][j];
                #pragma unroll
                for (int q = 0; q < 4; q++) {
                    dot = fmaf(__uint_as_float(w[q] << 16),         th[j*8 + q*2],     dot);
                    dot = fmaf(__uint_as_float(w[q] & 0xFFFF0000u), th[j*8 + q*2 + 1], dot);
                }
            }
            dots[rr] = dot;
        }
        #pragma unroll
        for (int off = 16; off; off >>= 1) {
            #pragma unroll
            for (int rr = 0; rr < 4; rr++)
                dots[rr] += __shfl_xor_sync(0xffffffffu, dots[rr], off);
        }
        if (lane == 0) {
            #pragma unroll
            for (int rr = 0; rr < 4; rr++) red_s[rr][wrp] = dots[rr];
        }
        __syncthreads();
        if (tid < 4) {
            float s = 0.0f;
            #pragma unroll
            for (int w = 0; w < 8; w++) s += red_s[tid][w];
            err_s[tid] = s - __ldg(&mp[rb + tid]);
        }
        __syncthreads();
        #pragma unroll
        for (int rr = 0; rr < 4; rr++) {
            const float err = err_s[rr];
            #pragma unroll
            for (int j = 0; j < 3; j++) {
                const uint32_t* w = (const uint32_t*)&u[p][rr][j];
                #pragma unroll
                for (int q = 0; q < 4; q++) {
                    gacc[j*8 + q*2]     = fmaf(err, __uint_as_float(w[q] << 16),         gacc[j*8 + q*2]);
                    gacc[j*8 + q*2 + 1] = fmaf(err, __uint_as_float(w[q] & 0xFFFF0000u), gacc[j*8 + q*2 + 1]);
                }
            }
        }
    }
    float* P = &g_part[(size_t)blockIdx.x * R_COLS + cbase];
    #pragma unroll
    for (int j = 0; j < 24; j++) P[j] = gacc[j];
}

// ---------------------------------------------------------------------------
// Two-stage deterministic reduce: 512 -> 32 -> theta
// ---------------------------------------------------------------------------
__global__ void gd_reduce1()
{
    int j = blockIdx.x * blockDim.x + threadIdx.x;
    int chunk = blockIdx.y;
    int b0 = chunk * (GD_BLOCKS / RED_CH);
    float s0 = 0.f, s1 = 0.f;
    #pragma unroll
    for (int b = 0; b < GD_BLOCKS / RED_CH; b += 2) {
        s0 += g_part[(size_t)(b0 + b) * R_COLS + j];
        s1 += g_part[(size_t)(b0 + b + 1) * R_COLS + j];
    }
    g_part2[(size_t)chunk * R_COLS + j] = s0 + s1;
}

__global__ void gd_reduce2_first(float scale)
{
    int j = blockIdx.x * blockDim.x + threadIdx.x;
    float s0 = 0.f, s1 = 0.f, s2 = 0.f, s3 = 0.f;
    #pragma unroll
    for (int b = 0; b < RED_CH; b += 4) {
        s0 += g_part2[(size_t)(b + 0) * R_COLS + j];
        s1 += g_part2[(size_t)(b + 1) * R_COLS + j];
        s2 += g_part2[(size_t)(b + 2) * R_COLS + j];
        s3 += g_part2[(size_t)(b + 3) * R_COLS + j];
    }
    g_theta[j] = -scale * ((s0 + s1) + (s2 + s3));
}

__global__ void gd_reduce2(float scale)
{
    int j = blockIdx.x * blockDim.x + threadIdx.x;
    float s0 = 0.f, s1 = 0.f, s2 = 0.f, s3 = 0.f;
    #pragma unroll
    for (int b = 0; b < RED_CH; b += 4) {
        s0 += g_part2[(size_t)(b + 0) * R_COLS + j];
        s1 += g_part2[(size_t)(b + 1) * R_COLS + j];
        s2 += g_part2[(size_t)(b + 2) * R_COLS + j];
        s3 += g_part2[(size_t)(b + 3) * R_COLS + j];
    }
    g_theta[j] -= scale * ((s0 + s1) + (s2 + s3));
}

__global__ void argmax_kernel()
{
    __shared__ float sums[6];
    int w = threadIdx.x >> 5, lane = threadIdx.x & 31;
    if (threadIdx.x < 192) {
        float s = 0.0f;
        for (int i = lane; i < H_SZ; i += 32) s += fabsf(g_theta[w * H_SZ + i]);
        #pragma unroll
        for (int off = 16; off; off >>= 1)
            s += __shfl_xor_sync(0xffffffffu, s, off);
        if (lane == 0) sums[w] = s;
    }
    __syncthreads();
    if (threadIdx.x == 0) {
        int best = 0; float bv = sums[0];
        #pragma unroll
        for (int g = 1; g < 6; g++)
            if (sums[g] > bv) { bv = sums[g]; best = g; }
        g_argmax = best;
    }
}

// 16 floats per thread (4 independent float4 loads -> MLP=4)
__global__ void gather_kernel(float* __restrict__ out_h)
{
    int t = blockIdx.x * blockDim.x + threadIdx.x;
    int e = t * 16;
    int b = e >> 10;
    int h = e & 1023;
    const int idx = g_argmax;
    const float4* src = (const float4*)&g_R[(size_t)b * R_COLS + idx * H_SZ + h];
    float4 v0 = src[0], v1 = src[1], v2 = src[2], v3 = src[3];
    float4* dst = (float4*)&out_h[e];
    dst[0] = v0; dst[1] = v1; dst[2] = v2; dst[3] = v3;
}

// ---------------------------------------------------------------------------
extern "C" void kernel_launch(void* const* d_in, const int* in_sizes, int n_in,
                              void* d_out, int out_size)
{
    const float* x      = (const float*)d_in[0];
    const float* hidden = (const float*)d_in[1];
    const float* c      = (const float*)d_in[2];
    const float* mp     = (const float*)d_in[3];
    const float* Wf_w = (const float*)d_in[4];
    const float* Wf_b = (const float*)d_in[5];
    const float* Uf_w = (const float*)d_in[6];
    const float* Wi_w = (const float*)d_in[7];
    const float* Wi_b = (const float*)d_in[8];
    const float* Ui_w = (const float*)d_in[9];
    const float* Wc_w = (const float*)d_in[10];
    const float* Wc_b = (const float*)d_in[11];
    const float* Uc_w = (const float*)d_in[12];
    const float* Wo_w = (const float*)d_in[13];
    const float* Wo_b = (const float*)d_in[14];
    const float* Uo_w = (const float*)d_in[15];

    float* out_h = (float*)d_out;
    float* out_c = out_h + (size_t)B_SZ * H_SZ;

    cudaFuncSetAttribute(gate_gemm_mma,
                         cudaFuncAttributeMaxDynamicSharedMemorySize, SMEM_TOTAL_B);

    __half* Ahh; cudaGetSymbolAddress((void**)&Ahh, g_Ahh);
    __half* Uhh; cudaGetSymbolAddress((void**)&Uhh, g_Uhh);

    const int nH16 = B_SZ * H_SZ / 16;          // 1048576
    const int nU16 = H_SZ * H_SZ / 16;          // 65536

    // GEMM is the 4th launch (the slot ncu captures)
    prep_f16_2<<<(nH16 + nU16 + 255) / 256, 256>>>(
        hidden, Ahh, nH16, Uf_w, Uhh + 0 * (size_t)H_SZ * H_SZ, nU16);
    prep_f16_2<<<(2 * nU16 + 255) / 256, 256>>>(
        Ui_w, Uhh + 1 * (size_t)H_SZ * H_SZ, nU16,
        Uc_w, Uhh + 2 * (size_t)H_SZ * H_SZ, nU16);
    prep_f16_2<<<(nU16 + 255) / 256, 256>>>(
        Uo_w, Uhh + 3 * (size_t)H_SZ * H_SZ, nU16,
        Uo_w, Uhh + 3 * (size_t)H_SZ * H_SZ, 0);

    dim3 ggrid(32, 64);
    gate_gemm_mma<<<ggrid, 512, SMEM_TOTAL_B>>>(x,
                                                Wf_w, Wi_w, Wc_w, Wo_w,
                                                Wf_b, Wi_b, Wc_b, Wo_b);

    const float scale = 2.0f * GD_LR_K / (float)B_SZ;
    dim3 r1grid(R_COLS / 256, RED_CH);

    cellstate_gd0<<<GD_BLOCKS, 256>>>(c, mp, out_c);
    gd_reduce1<<<r1grid, 256>>>();
    gd_reduce2_first<<<R_COLS / 256, 256>>>(scale);

    for (int it = 1; it < GD_ITERS_K; it++) {
        gd_pass<<<GD_BLOCKS, 256>>>(mp);
        gd_reduce1<<<r1grid, 256>>>();
        gd_reduce2<<<R_COLS / 256, 256>>>(scale);
    }

    argmax_kernel<<<1, 192>>>();
    gather_kernel<<<(B_SZ * H_SZ / 16) / 256, 256>>>(out_h);
}